// round 8
// baseline (speedup 1.0000x reference)
#include <cuda_runtime.h>
#include <cstdint>

#define B_DIM 4096
#define F_DIM 16384
#define G_DIM 512
#define S_DIM 32
#define N_IDX (G_DIM * S_DIM)   // 16384 == F_DIM: idx is a permutation of features

#define N_SM 148
#define CTAS_PER_SM 6
#define GRID_PERSIST (N_SM * CTAS_PER_SM)   // 888 resident CTAs, single wave

// Folded per-feature weight pw[f] = w_group[j]*fc_kernel[j/S] where idx[j]==f.
// group_idx is a permutation of [0, F): every slot overwritten each launch,
// so no zeroing and no atomics needed.
__device__ float g_pw[F_DIM];
__device__ unsigned int g_row_ctr;   // dynamic work queue head

// Scatter with in-kernel dtype detection (JAX may hand int32 despite int64 in
// the reference: little-endian int64 < 2^31 has every odd 32-bit word == 0).
// Also resets the work-queue counter for the row kernel (runs before it in
// stream order, so the reset is always visible).
__global__ void scatter_weights_kernel(const unsigned int* __restrict__ idx_words,
                                       const float* __restrict__ w_group,
                                       const float* __restrict__ fc_kernel) {
    if (blockIdx.x == 0 && threadIdx.x == 0) g_row_ctr = 0u;

    __shared__ int s_is64;
    if (threadIdx.x == 0) {
        int is64 = 1;
        #pragma unroll
        for (int j = 0; j < 32; j++) {
            if (idx_words[2 * j + 1] != 0u) { is64 = 0; break; }
        }
        s_is64 = is64;
    }
    __syncthreads();

    int j = blockIdx.x * blockDim.x + threadIdx.x;  // j in [0, N_IDX)
    if (j < N_IDX) {
        int g = j / S_DIM;
        float w = w_group[j] * fc_kernel[g];  // UNITS == 1
        long long f;
        if (s_is64) {
            f = ((const long long*)idx_words)[j];
        } else {
            f = (long long)((const int*)idx_words)[j];
        }
        if (f >= 0 && f < F_DIM) {
            g_pw[(int)f] = w;   // permutation: exactly one writer per slot
        }
    }
}

// Persistent CTAs pulling rows from a dynamic queue: no wave transitions,
// balanced tail. Inner loop identical to the proven 43.4us/79% DRAM shape.
__global__ void __launch_bounds__(256) row_dot_persist_kernel(const float* __restrict__ x,
                                                              float* __restrict__ out) {
    const int tid = threadIdx.x;
    const int wid = tid >> 5, lid = tid & 31;
    const float4* __restrict__ pw = reinterpret_cast<const float4*>(g_pw);

    __shared__ float warp_sum[8];
    __shared__ unsigned int s_row;

    for (;;) {
        if (tid == 0) s_row = atomicAdd(&g_row_ctr, 1u);
        __syncthreads();
        const unsigned int b = s_row;
        if (b >= B_DIM) break;

        const float4* __restrict__ xr =
            reinterpret_cast<const float4*>(x + (size_t)b * F_DIM);

        float acc = 0.0f;
        // F/4 = 4096 float4; 256 threads -> 16 iterations each
        #pragma unroll 16
        for (int i = tid; i < F_DIM / 4; i += 256) {
            float4 a = __ldcs(&xr[i]);   // streaming: x is read exactly once
            float4 w = __ldg(&pw[i]);    // pw is hot in L1/L2
            acc += a.x * w.x + a.y * w.y + a.z * w.z + a.w * w.w;
        }

        // Warp reduce
        #pragma unroll
        for (int off = 16; off > 0; off >>= 1)
            acc += __shfl_down_sync(0xFFFFFFFFu, acc, off);

        if (lid == 0) warp_sum[wid] = acc;
        __syncthreads();
        if (wid == 0) {
            float v = (lid < 8) ? warp_sum[lid] : 0.0f;
            #pragma unroll
            for (int off = 4; off > 0; off >>= 1)
                v += __shfl_down_sync(0xFFFFFFFFu, v, off);
            if (lid == 0) out[b] = v;
        }
        __syncthreads();   // protect s_row / warp_sum reuse
    }
}

extern "C" void kernel_launch(void* const* d_in, const int* in_sizes, int n_in,
                              void* d_out, int out_size) {
    const float* x         = (const float*)d_in[0];
    const void*  group_idx = d_in[1];
    const float* w_group   = (const float*)d_in[2];
    const float* fc_kernel = (const float*)d_in[3];
    float* out = (float*)d_out;

    scatter_weights_kernel<<<(N_IDX + 255) / 256, 256>>>(
        (const unsigned int*)group_idx, w_group, fc_kernel);
    row_dot_persist_kernel<<<GRID_PERSIST, 256>>>(x, out);
}

// round 9
// speedup vs baseline: 1.0265x; 1.0265x over previous
#include <cuda_runtime.h>
#include <cstdint>

#define B_DIM 4096
#define F_DIM 16384
#define G_DIM 512
#define S_DIM 32
#define N_IDX (G_DIM * S_DIM)   // 16384 == F_DIM: idx is a permutation of features

// Folded per-feature weight pw[f] = w_group[j]*fc_kernel[j/S] where idx[j]==f.
// group_idx is a permutation of [0, F): every slot overwritten each launch,
// so no zeroing and no atomics needed.
__device__ float g_pw[F_DIM];

// Scatter with in-kernel dtype detection (JAX may hand int32 despite int64 in
// the reference: little-endian int64 < 2^31 has every odd 32-bit word == 0).
// Each CTA signals PDL completion right after its pw stores so the row kernel
// (launched with programmatic serialization) can start as early as possible.
__global__ void scatter_weights_kernel(const unsigned int* __restrict__ idx_words,
                                       const float* __restrict__ w_group,
                                       const float* __restrict__ fc_kernel) {
    __shared__ int s_is64;
    if (threadIdx.x == 0) {
        int is64 = 1;
        #pragma unroll
        for (int j = 0; j < 32; j++) {
            if (idx_words[2 * j + 1] != 0u) { is64 = 0; break; }
        }
        s_is64 = is64;
    }
    __syncthreads();

    int j = blockIdx.x * blockDim.x + threadIdx.x;  // j in [0, N_IDX)
    if (j < N_IDX) {
        int g = j / S_DIM;
        float w = w_group[j] * fc_kernel[g];  // UNITS == 1
        long long f;
        if (s_is64) {
            f = ((const long long*)idx_words)[j];
        } else {
            f = (long long)((const int*)idx_words)[j];
        }
        if (f >= 0 && f < F_DIM) {
            g_pw[(int)f] = w;   // permutation: exactly one writer per slot
        }
    }
#if __CUDA_ARCH__ >= 900
    cudaTriggerProgrammaticLaunchCompletion();
#endif
}

// One block per row b: out[b] = dot(x[b, :], pw).  Pure HBM stream of x.
// Proven shape: 43.4us @ DRAM 79%, beats 4-row (R5) and persistent (R7) variants.
__global__ void __launch_bounds__(256) row_dot_kernel(const float* __restrict__ x,
                                                      float* __restrict__ out) {
    const int b = blockIdx.x;
    const int tid = threadIdx.x;

    const float4* __restrict__ xr = reinterpret_cast<const float4*>(x + (size_t)b * F_DIM);
    const float4* __restrict__ pw = reinterpret_cast<const float4*>(g_pw);

#if __CUDA_ARCH__ >= 900
    // Wait for the scatter's pw writes; launch latency is overlapped via PDL.
    cudaGridDependencySynchronize();
#endif

    float acc = 0.0f;
    // F/4 = 4096 float4; 256 threads -> 16 iterations each
    #pragma unroll 16
    for (int i = tid; i < F_DIM / 4; i += 256) {
        float4 a = __ldcs(&xr[i]);   // streaming: x is read exactly once
        float4 w = __ldg(&pw[i]);    // pw is hot in L2/L1
        acc += a.x * w.x + a.y * w.y + a.z * w.z + a.w * w.w;
    }

    // Warp reduce
    #pragma unroll
    for (int off = 16; off > 0; off >>= 1)
        acc += __shfl_down_sync(0xFFFFFFFFu, acc, off);

    // Block reduce across 8 warps
    __shared__ float warp_sum[8];
    int wid = tid >> 5, lid = tid & 31;
    if (lid == 0) warp_sum[wid] = acc;
    __syncthreads();
    if (wid == 0) {
        float v = (lid < 8) ? warp_sum[lid] : 0.0f;
        #pragma unroll
        for (int off = 4; off > 0; off >>= 1)
            v += __shfl_down_sync(0xFFFFFFFFu, v, off);
        if (lid == 0) out[b] = v;
    }
}

extern "C" void kernel_launch(void* const* d_in, const int* in_sizes, int n_in,
                              void* d_out, int out_size) {
    const float* x         = (const float*)d_in[0];
    const void*  group_idx = d_in[1];
    const float* w_group   = (const float*)d_in[2];
    const float* fc_kernel = (const float*)d_in[3];
    float* out = (float*)d_out;

    scatter_weights_kernel<<<(N_IDX + 255) / 256, 256>>>(
        (const unsigned int*)group_idx, w_group, fc_kernel);

    // Launch row_dot with programmatic stream serialization (PDL): it may
    // begin (and hide its launch latency) before scatter fully retires;
    // cudaGridDependencySynchronize() inside guards the pw dependency.
    cudaLaunchConfig_t cfg = {};
    cfg.gridDim  = dim3(B_DIM, 1, 1);
    cfg.blockDim = dim3(256, 1, 1);
    cfg.dynamicSmemBytes = 0;
    cfg.stream = 0;  // legacy default stream (the capture stream)
    cudaLaunchAttribute attrs[1];
    attrs[0].id = cudaLaunchAttributeProgrammaticStreamSerialization;
    attrs[0].val.programmaticStreamSerializationAllowed = 1;
    cfg.attrs = attrs;
    cfg.numAttrs = 1;
    cudaLaunchKernelEx(&cfg, row_dot_kernel, x, out);
}